// round 1
// baseline (speedup 1.0000x reference)
#include <cuda_runtime.h>
#include <cuda_bf16.h>

#define N_G   512
#define W_IMG 256
#define H_IMG 256
#define TILE  16

// Sorted per-gaussian data (written by prep, read by render)
__device__ float4 d_cull[N_G]; // mx, my, r2, blue
__device__ float4 d_gA[N_G];   // mx, my, ia, ibc
__device__ float4 d_gB[N_G];   // id, coef(=valid*opac*norm), red, green

// ---------------------------------------------------------------------------
// Kernel 1: per-gaussian preprocessing + stable depth sort (rank via O(N^2))
// One block of 512 threads.
// ---------------------------------------------------------------------------
__global__ void prep_kernel(const float* __restrict__ means,
                            const float* __restrict__ covs,
                            const float* __restrict__ colors,
                            const float* __restrict__ opac,
                            const float* __restrict__ Km,
                            const float* __restrict__ Rm,
                            const float* __restrict__ tv)
{
    __shared__ float sdepth[N_G];
    const int i = threadIdx.x;

    const float m0 = means[3*i], m1 = means[3*i+1], m2 = means[3*i+2];
    const float R00=Rm[0],R01=Rm[1],R02=Rm[2];
    const float R10=Rm[3],R11=Rm[4],R12=Rm[5];
    const float R20=Rm[6],R21=Rm[7],R22=Rm[8];

    // cam = mean @ R^T + t
    const float X = R00*m0 + R01*m1 + R02*m2 + tv[0];
    const float Y = R10*m0 + R11*m1 + R12*m2 + tv[1];
    const float Z = R20*m0 + R21*m1 + R22*m2 + tv[2];

    const float depth = fmaxf(Z, 1.0f);
    sdepth[i] = depth;
    __syncthreads();

    // stable rank (matches jnp.argsort stable semantics)
    int rank = 0;
#pragma unroll 8
    for (int j = 0; j < N_G; j++) {
        const float dj = sdepth[j];
        rank += (dj < depth) || (dj == depth && j < i);
    }

    // screen projection: screen = cam @ K^T ; means2D = screen.xy / screen.z
    const float K00=Km[0],K01=Km[1],K02=Km[2];
    const float K10=Km[3],K11=Km[4],K12=Km[5];
    const float K20=Km[6],K21=Km[7],K22=Km[8];
    const float sx = K00*X + K01*Y + K02*Z;
    const float sy = K10*X + K11*Y + K12*Z;
    const float sz = K20*X + K21*Y + K22*Z;
    const float mx2 = sx / sz;
    const float my2 = sy / sz;

    // Jacobian rows (fx=K00, fy=K11, using raw Z like the reference)
    const float fx = K00, fy = K11;
    const float j00 =  fx / Z;
    const float j02 = -fx * X / (Z * Z);
    const float j11 =  fy / Z;
    const float j12 = -fy * Y / (Z * Z);

    // covs_cam = R * C * R^T
    float C[3][3];
#pragma unroll
    for (int r = 0; r < 3; r++)
#pragma unroll
        for (int c = 0; c < 3; c++)
            C[r][c] = covs[9*i + 3*r + c];

    float Rm3[3][3] = {{R00,R01,R02},{R10,R11,R12},{R20,R21,R22}};
    float M[3][3], CC[3][3];
#pragma unroll
    for (int r = 0; r < 3; r++)
#pragma unroll
        for (int c = 0; c < 3; c++)
            M[r][c] = Rm3[r][0]*C[0][c] + Rm3[r][1]*C[1][c] + Rm3[r][2]*C[2][c];
#pragma unroll
    for (int r = 0; r < 3; r++)
#pragma unroll
        for (int c = 0; c < 3; c++)
            CC[r][c] = M[r][0]*Rm3[c][0] + M[r][1]*Rm3[c][1] + M[r][2]*Rm3[c][2];

    // cov2D = J * CC * J^T   (J row0 = (j00,0,j02), row1 = (0,j11,j12))
    float v0[3], v1[3];
#pragma unroll
    for (int k = 0; k < 3; k++) {
        v0[k] = CC[k][0]*j00 + CC[k][2]*j02;
        v1[k] = CC[k][1]*j11 + CC[k][2]*j12;
    }
    float a = j00*v0[0] + j02*v0[2];
    float c = j11*v0[1] + j12*v0[2];
    float b = j00*v1[0] + j02*v1[2];
    float d = j11*v1[1] + j12*v1[2];
    a += 1e-4f;
    d += 1e-4f;

    const float det  = a*d - b*c;
    const float ia   =  d / det;
    const float ibc  = (-b - c) / det;
    const float idv  =  a / det;
    const float norm = 1.0f / (2.0f * 3.14159265358979323846f * sqrtf(det));

    const bool  valid = (depth > 1.0f) && (depth < 50.0f);
    const float coef  = valid ? opac[i] * norm : 0.0f;

    // conservative influence radius: alpha <= coef * exp(-0.5*d^2/lam_max)
    const float lam = 0.5f*(a+d) + sqrtf(fmaxf(0.0f, 0.25f*(a-d)*(a-d) + b*c));
    float r2 = -1.0f;
    if (coef > 1e-12f) {
        const float lg = logf(coef * 1e12f);
        r2 = (lg > 0.0f) ? 2.0f * lam * lg : -1.0f;
    }

    d_cull[rank] = make_float4(mx2, my2, r2, colors[3*i + 2]);
    d_gA[rank]   = make_float4(mx2, my2, ia, ibc);
    d_gB[rank]   = make_float4(idv, coef, colors[3*i + 0], colors[3*i + 1]);
}

// ---------------------------------------------------------------------------
// Kernel 2: tile-based render. Block = 16x16 threads = 16x16 pixel tile.
// Phase 1: order-preserving cull+compact into shared memory.
// Phase 2: per-pixel front-to-back alpha compositing.
// ---------------------------------------------------------------------------
__global__ __launch_bounds__(256) void render_kernel(float* __restrict__ out)
{
    __shared__ float4 s0[N_G];   // mx, my, ia, ibc
    __shared__ float4 s1[N_G];   // id, coef, r, g
    __shared__ float  s2[N_G];   // b
    __shared__ int    s_wc[8];
    __shared__ int    s_cnt;

    const int tx  = threadIdx.x, ty = threadIdx.y;
    const int tid = ty * TILE + tx;
    const int x0  = blockIdx.x * TILE;
    const int y0  = blockIdx.y * TILE;

    const float fx0 = (float)x0,        fy0 = (float)y0;
    const float fx1 = (float)(x0 + TILE - 1), fy1 = (float)(y0 + TILE - 1);

    if (tid == 0) s_cnt = 0;
    __syncthreads();

    const int warp = tid >> 5;
    const int lane = tid & 31;

    for (int base = 0; base < N_G; base += 256) {
        const int gi = base + tid;
        const float4 cu = d_cull[gi];
        const float dxm = fmaxf(0.0f, fmaxf(fx0 - cu.x, cu.x - fx1));
        const float dym = fmaxf(0.0f, fmaxf(fy0 - cu.y, cu.y - fy1));
        const bool ins  = (dxm*dxm + dym*dym) <= cu.z;   // r2 < 0 => culled

        const unsigned bal = __ballot_sync(0xffffffffu, ins);
        if (lane == 0) s_wc[warp] = __popc(bal);
        __syncthreads();

        int off = s_cnt;
        for (int w = 0; w < warp; w++) off += s_wc[w];
        if (ins) {
            const int pos = off + __popc(bal & ((1u << lane) - 1u));
            s0[pos] = d_gA[gi];
            s1[pos] = d_gB[gi];
            s2[pos] = cu.w;
        }
        __syncthreads();
        if (tid == 0) {
            int tot = 0;
            for (int w = 0; w < 8; w++) tot += s_wc[w];
            s_cnt += tot;
        }
        __syncthreads();
    }

    const int M = s_cnt;
    const float px = (float)(x0 + tx);
    const float py = (float)(y0 + ty);

    float T = 1.0f, cr = 0.0f, cg = 0.0f, cb = 0.0f;
#pragma unroll 4
    for (int i = 0; i < M; i++) {
        const float4 g0 = s0[i];
        const float4 g1 = s1[i];
        const float  bl = s2[i];
        const float dx = px - g0.x;
        const float dy = py - g0.y;
        const float q  = g0.z*dx*dx + g0.w*dx*dy + g1.x*dy*dy;
        const float alpha = g1.y * __expf(-0.5f * q);
        const float w = alpha * T;
        cr += w * g1.z;
        cg += w * g1.w;
        cb += w * bl;
        T *= (1.0f - alpha);
    }

    const int oidx = ((y0 + ty) * W_IMG + (x0 + tx)) * 3;
    out[oidx + 0] = cr;
    out[oidx + 1] = cg;
    out[oidx + 2] = cb;
}

// ---------------------------------------------------------------------------
extern "C" void kernel_launch(void* const* d_in, const int* in_sizes, int n_in,
                              void* d_out, int out_size)
{
    const float* means  = (const float*)d_in[0];
    const float* covs   = (const float*)d_in[1];
    const float* colors = (const float*)d_in[2];
    const float* opac   = (const float*)d_in[3];
    const float* Km     = (const float*)d_in[4];
    const float* Rm     = (const float*)d_in[5];
    const float* tv     = (const float*)d_in[6];
    // d_in[7] = pixels grid (implicit: pixel (x,y) = (w,h))

    prep_kernel<<<1, N_G>>>(means, covs, colors, opac, Km, Rm, tv);

    dim3 block(TILE, TILE);
    dim3 grid(W_IMG / TILE, H_IMG / TILE);
    render_kernel<<<grid, block>>>((float*)d_out);
}

// round 2
// speedup vs baseline: 1.4373x; 1.4373x over previous
#include <cuda_runtime.h>
#include <cuda_bf16.h>

#define N_G   512
#define W_IMG 256
#define H_IMG 256
#define TILE  16
#define LOG2E 1.4426950408889634f

// Sorted per-gaussian data (written by prep, read by render)
__device__ float4 d_cull[N_G]; // mx, my, r2, pb(=coef*blue)
__device__ float4 d_gA[N_G];   // mx, my, iaS, ibcS   (S = -0.5*log2e folded in)
__device__ float4 d_gB[N_G];   // idS, coef, pr(=coef*red), pg(=coef*green)

// ---------------------------------------------------------------------------
// Kernel 1: per-gaussian preprocessing + stable depth sort.
// 8 blocks x 64 threads; each block redundantly computes all 512 depths
// (cooperatively into shared), then handles 64 gaussians fully.
// ---------------------------------------------------------------------------
__global__ __launch_bounds__(64) void prep_kernel(const float* __restrict__ means,
                            const float* __restrict__ covs,
                            const float* __restrict__ colors,
                            const float* __restrict__ opac,
                            const float* __restrict__ Km,
                            const float* __restrict__ Rm,
                            const float* __restrict__ tv)
{
    __shared__ float sdepth[N_G];
    const int t = threadIdx.x;            // 0..63
    const int i = blockIdx.x * 64 + t;    // this thread's gaussian

    const float R00=Rm[0],R01=Rm[1],R02=Rm[2];
    const float R10=Rm[3],R11=Rm[4],R12=Rm[5];
    const float R20=Rm[6],R21=Rm[7],R22=Rm[8];
    const float t0=tv[0], t1=tv[1], t2=tv[2];

    // all 512 depths into shared (8 per thread, coalesced)
#pragma unroll
    for (int k = 0; k < 8; k++) {
        const int j = k * 64 + t;
        const float m0 = means[3*j], m1 = means[3*j+1], m2 = means[3*j+2];
        const float Zj = R20*m0 + R21*m1 + R22*m2 + t2;
        sdepth[j] = fmaxf(Zj, 1.0f);
    }
    __syncthreads();

    // own camera-space position
    const float m0 = means[3*i], m1 = means[3*i+1], m2 = means[3*i+2];
    const float X = R00*m0 + R01*m1 + R02*m2 + t0;
    const float Y = R10*m0 + R11*m1 + R12*m2 + t1;
    const float Z = R20*m0 + R21*m1 + R22*m2 + t2;
    const float depth = fmaxf(Z, 1.0f);

    // stable rank (matches stable argsort): 2 accumulators, unrolled
    int ra = 0, rb = 0;
#pragma unroll 8
    for (int j = 0; j < N_G; j += 2) {
        const float d0 = sdepth[j];
        const float d1 = sdepth[j+1];
        ra += (d0 < depth) || (d0 == depth && j     < i);
        rb += (d1 < depth) || (d1 == depth && (j+1) < i);
    }
    const int rank = ra + rb;

    // screen projection
    const float K00=Km[0],K01=Km[1],K02=Km[2];
    const float K10=Km[3],K11=Km[4],K12=Km[5];
    const float K20=Km[6],K21=Km[7],K22=Km[8];
    const float sx = K00*X + K01*Y + K02*Z;
    const float sy = K10*X + K11*Y + K12*Z;
    const float sz = K20*X + K21*Y + K22*Z;
    const float mx2 = sx / sz;
    const float my2 = sy / sz;

    // Jacobian
    const float fx = K00, fy = K11;
    const float j00 =  fx / Z;
    const float j02 = -fx * X / (Z * Z);
    const float j11 =  fy / Z;
    const float j12 = -fy * Y / (Z * Z);

    // covs_cam = R * C * R^T
    float C[3][3];
#pragma unroll
    for (int r = 0; r < 3; r++)
#pragma unroll
        for (int c = 0; c < 3; c++)
            C[r][c] = covs[9*i + 3*r + c];

    const float Rm3[3][3] = {{R00,R01,R02},{R10,R11,R12},{R20,R21,R22}};
    float M[3][3], CC[3][3];
#pragma unroll
    for (int r = 0; r < 3; r++)
#pragma unroll
        for (int c = 0; c < 3; c++)
            M[r][c] = Rm3[r][0]*C[0][c] + Rm3[r][1]*C[1][c] + Rm3[r][2]*C[2][c];
#pragma unroll
    for (int r = 0; r < 3; r++)
#pragma unroll
        for (int c = 0; c < 3; c++)
            CC[r][c] = M[r][0]*Rm3[c][0] + M[r][1]*Rm3[c][1] + M[r][2]*Rm3[c][2];

    // cov2D = J * CC * J^T
    float v0[3], v1[3];
#pragma unroll
    for (int k = 0; k < 3; k++) {
        v0[k] = CC[k][0]*j00 + CC[k][2]*j02;
        v1[k] = CC[k][1]*j11 + CC[k][2]*j12;
    }
    float a = j00*v0[0] + j02*v0[2];
    float c = j11*v0[1] + j12*v0[2];
    float b = j00*v1[0] + j02*v1[2];
    float d = j11*v1[1] + j12*v1[2];
    a += 1e-4f;
    d += 1e-4f;

    const float det  = a*d - b*c;
    const float S    = -0.5f * LOG2E;            // fold into quad form: exp -> exp2
    const float iaS  = S * ( d / det);
    const float ibcS = S * ((-b - c) / det);
    const float idS  = S * ( a / det);
    const float norm = 1.0f / (2.0f * 3.14159265358979323846f * sqrtf(det));

    const bool  valid = (depth > 1.0f) && (depth < 50.0f);
    const float coef  = valid ? opac[i] * norm : 0.0f;

    // conservative influence radius at alpha threshold 1e-9
    const float lam = 0.5f*(a+d) + sqrtf(fmaxf(0.0f, 0.25f*(a-d)*(a-d) + b*c));
    float r2 = -1.0f;
    if (coef > 0.0f) {
        const float lg = logf(coef * 1e9f);
        r2 = (lg > 0.0f) ? 2.0f * lam * lg : -1.0f;
    }

    const float cr = colors[3*i + 0], cg = colors[3*i + 1], cb = colors[3*i + 2];
    d_cull[rank] = make_float4(mx2, my2, r2, coef * cb);
    d_gA[rank]   = make_float4(mx2, my2, iaS, ibcS);
    d_gB[rank]   = make_float4(idS, coef, coef * cr, coef * cg);
}

// ---------------------------------------------------------------------------
// Kernel 2: tile render. Block = (16,8) = 128 threads, 16x16-pixel tile,
// each thread composites 2 pixels (same x, y and y+8): shared dx and ia*dx.
// ---------------------------------------------------------------------------
__global__ __launch_bounds__(128) void render_kernel(float* __restrict__ out)
{
    __shared__ float4 s0[N_G];   // mx, my, iaS, ibcS
    __shared__ float4 s1[N_G];   // idS, coef, pr, pg
    __shared__ float  s2[N_G];   // pb
    __shared__ int    s_wc[4];
    __shared__ int    s_cnt;

    const int tx  = threadIdx.x;           // 0..15
    const int ty  = threadIdx.y;           // 0..7
    const int tid = ty * TILE + tx;        // 0..127
    const int x0  = blockIdx.x * TILE;
    const int y0  = blockIdx.y * TILE;

    const float fx0 = (float)x0,              fy0 = (float)y0;
    const float fx1 = (float)(x0 + TILE - 1), fy1 = (float)(y0 + TILE - 1);

    if (tid == 0) s_cnt = 0;
    __syncthreads();

    const int warp = tid >> 5;
    const int lane = tid & 31;

    // order-preserving cull + compact
    for (int base = 0; base < N_G; base += 128) {
        const int gi = base + tid;
        const float4 cu = d_cull[gi];
        const float dxm = fmaxf(0.0f, fmaxf(fx0 - cu.x, cu.x - fx1));
        const float dym = fmaxf(0.0f, fmaxf(fy0 - cu.y, cu.y - fy1));
        const bool ins  = (dxm*dxm + dym*dym) <= cu.z;   // r2 < 0 => culled

        const unsigned bal = __ballot_sync(0xffffffffu, ins);
        if (lane == 0) s_wc[warp] = __popc(bal);
        __syncthreads();

        int off = s_cnt;
        for (int w = 0; w < warp; w++) off += s_wc[w];
        if (ins) {
            const int pos = off + __popc(bal & ((1u << lane) - 1u));
            s0[pos] = d_gA[gi];
            s1[pos] = d_gB[gi];
            s2[pos] = cu.w;
        }
        __syncthreads();
        if (tid == 0) s_cnt += s_wc[0] + s_wc[1] + s_wc[2] + s_wc[3];
        __syncthreads();
    }

    const int M = s_cnt;
    const float px  = (float)(x0 + tx);
    const float pyA = (float)(y0 + ty);
    const float pyB = (float)(y0 + ty + 8);

    float TA = 1.0f, rA = 0.0f, gA = 0.0f, bA = 0.0f;
    float TB = 1.0f, rB = 0.0f, gB = 0.0f, bB = 0.0f;

#pragma unroll 2
    for (int i = 0; i < M; i++) {
        const float4 g0 = s0[i];
        const float4 g1 = s1[i];
        const float  pb = s2[i];

        const float dx  = px - g0.x;
        const float u   = g0.z * dx;            // iaS*dx, shared by both pixels
        const float dyA = pyA - g0.y;
        const float dyB = pyB - g0.y;

        const float tA = fmaf(g0.w, dyA, u);
        const float tB = fmaf(g0.w, dyB, u);
        const float vA = g1.x * dyA * dyA;
        const float vB = g1.x * dyB * dyB;
        const float qA = fmaf(tA, dx, vA);      // already scaled for exp2
        const float qB = fmaf(tB, dx, vB);

        float eA, eB;
        asm("ex2.approx.f32 %0, %1;" : "=f"(eA) : "f"(qA));
        asm("ex2.approx.f32 %0, %1;" : "=f"(eB) : "f"(qB));

        const float wA = TA * eA;
        const float wB = TB * eB;
        rA = fmaf(wA, g1.z, rA);  gA = fmaf(wA, g1.w, gA);  bA = fmaf(wA, pb, bA);
        rB = fmaf(wB, g1.z, rB);  gB = fmaf(wB, g1.w, gB);  bB = fmaf(wB, pb, bB);
        TA = fmaf(-wA, g1.y, TA);
        TB = fmaf(-wB, g1.y, TB);
    }

    const int pA = ((y0 + ty)     * W_IMG + (x0 + tx)) * 3;
    const int pB = ((y0 + ty + 8) * W_IMG + (x0 + tx)) * 3;
    out[pA + 0] = rA;  out[pA + 1] = gA;  out[pA + 2] = bA;
    out[pB + 0] = rB;  out[pB + 1] = gB;  out[pB + 2] = bB;
}

// ---------------------------------------------------------------------------
extern "C" void kernel_launch(void* const* d_in, const int* in_sizes, int n_in,
                              void* d_out, int out_size)
{
    const float* means  = (const float*)d_in[0];
    const float* covs   = (const float*)d_in[1];
    const float* colors = (const float*)d_in[2];
    const float* opac   = (const float*)d_in[3];
    const float* Km     = (const float*)d_in[4];
    const float* Rm     = (const float*)d_in[5];
    const float* tv     = (const float*)d_in[6];

    prep_kernel<<<8, 64>>>(means, covs, colors, opac, Km, Rm, tv);

    dim3 block(TILE, 8);
    dim3 grid(W_IMG / TILE, H_IMG / TILE);
    render_kernel<<<grid, block>>>((float*)d_out);
}